// round 2
// baseline (speedup 1.0000x reference)
#include <cuda_runtime.h>

// ---------------------------------------------------------------------------
// Spatial_Attention_layer: out = softmax_axis1( V_s @ sigmoid(W2^T M + b_s) )
// where M[u][j] = sum_b a_b[u] * r_b[j],
//       a_b[v] = sum_t W1[t] x[b,t,v],  r_b[v] = sum_t W3[t] x[b,t,v]
// B = 131072, T = 5, V = 60 (padded to 64)
// ---------------------------------------------------------------------------

#define NTHREADS 256
#define GRP       8               // batches per smem stage
#define BPC      256              // batches per CTA
#define NGRP     (BPC / GRP)      // 32
#define F4PG     (GRP * 75)       // 600 float4 per group

typedef unsigned long long u64;

__device__ float g_Maccum[64 * 64];

// ---- packed f32x2 helpers (FFMA2 only reachable via PTX) -------------------
__device__ __forceinline__ void ffma2(u64 &d, u64 a, u64 b) {
    asm("fma.rn.f32x2 %0, %1, %2, %3;" : "=l"(d) : "l"(a), "l"(b), "l"(d));
}
__device__ __forceinline__ void unpack2(u64 v, float &lo, float &hi) {
    asm("mov.b64 {%0, %1}, %2;" : "=f"(lo), "=f"(hi) : "l"(v));
}

// ---- cp.async helpers ------------------------------------------------------
__device__ __forceinline__ void cp_async16(void *smem, const void *g) {
    unsigned saddr = (unsigned)__cvta_generic_to_shared(smem);
    asm volatile("cp.async.cg.shared.global [%0], [%1], 16;" :: "r"(saddr), "l"(g));
}
__device__ __forceinline__ void cp_commit() { asm volatile("cp.async.commit_group;"); }
template <int N>
__device__ __forceinline__ void cp_wait() { asm volatile("cp.async.wait_group %0;" :: "n"(N)); }

__device__ __forceinline__ void stage_group(float4 *dst, const float4 *src, int tid) {
    // 600 float4 over 256 threads: 2 full passes + partial third (tid < 88)
    cp_async16(dst + tid,       src + tid);
    cp_async16(dst + tid + 256, src + tid + 256);
    if (tid < F4PG - 512) cp_async16(dst + tid + 512, src + tid + 512);
    cp_commit();
}

// ---------------------------------------------------------------------------
__global__ void __launch_bounds__(256) zero_kernel() {
    g_Maccum[blockIdx.x * blockDim.x + threadIdx.x] = 0.0f;
}

// ---------------------------------------------------------------------------
// Stage 1: stream x, accumulate M = sum_b a_b (outer) r_b, atomically reduce.
// Thread (tu, tj) owns a 4x4 tile of the 64x64 accumulator.
// ---------------------------------------------------------------------------
__global__ void __launch_bounds__(NTHREADS, 4)
stage1_kernel(const float *__restrict__ x,
              const float *__restrict__ W1p,
              const float *__restrict__ W3p) {
    __shared__ float4 xs[2][F4PG];       // 2 x 8 batches x 300 floats = 19.2 KB
    __shared__ float2 a2s[GRP][64];      // a pre-duplicated {a,a}      = 4 KB
    __shared__ float  rs[GRP][64];       //                              = 2 KB

    const int tid = threadIdx.x;
    const long base_batch = (long)blockIdx.x * BPC;
    const float4 *gx = (const float4 *)x + base_batch * 75;  // 300 floats = 75 f4 / batch

    float w1[5], w3[5];
#pragma unroll
    for (int t = 0; t < 5; t++) { w1[t] = W1p[t]; w3[t] = W3p[t]; }

    u64 acc[4][2];
#pragma unroll
    for (int u = 0; u < 4; u++) { acc[u][0] = 0ull; acc[u][1] = 0ull; }

    const int tu4 = (tid >> 4) * 4;   // row block  (0..60 step 4)
    const int tj4 = (tid & 15) * 4;   // col block  (0..60 step 4)

    // prologue: stage group 0
    stage_group(xs[0], gx, tid);

    for (int grp = 0; grp < NGRP; grp++) {
        const int buf = grp & 1;
        if (grp + 1 < NGRP) {
            stage_group(xs[buf ^ 1], gx + (long)(grp + 1) * F4PG, tid);
            cp_wait<1>();   // group grp complete; grp+1 in flight
        } else {
            cp_wait<0>();
        }
        __syncthreads();    // xs[buf] visible; prev outer done with a2s/rs

        // a (duplicated) and r for the GRP staged batches: 2 iters exactly
#pragma unroll
        for (int it = 0; it < (GRP * 64) / NTHREADS; it++) {
            const int idx = tid + it * NTHREADS;
            const int g = idx >> 6, v = idx & 63;
            float s1 = 0.0f, s3 = 0.0f;
            if (v < 60) {
                const float *xb = ((const float *)&xs[buf][0]) + g * 300;
#pragma unroll
                for (int t = 0; t < 5; t++) {
                    const float xv = xb[t * 60 + v];
                    s1 = fmaf(w1[t], xv, s1);
                    s3 = fmaf(w3[t], xv, s3);
                }
            }
            a2s[g][v] = make_float2(s1, s1);
            rs[g][v]  = s3;
        }
        __syncthreads();

        // rank-1 updates: 3 x LDS.128 + 8 x FFMA2 per batch per thread
#pragma unroll 2
        for (int g = 0; g < GRP; g++) {
            const ulonglong2 *pa = (const ulonglong2 *)&a2s[g][tu4];
            const ulonglong2 aA = pa[0];
            const ulonglong2 aB = pa[1];
            const ulonglong2 rr = *(const ulonglong2 *)&rs[g][tj4];
            ffma2(acc[0][0], aA.x, rr.x); ffma2(acc[0][1], aA.x, rr.y);
            ffma2(acc[1][0], aA.y, rr.x); ffma2(acc[1][1], aA.y, rr.y);
            ffma2(acc[2][0], aB.x, rr.x); ffma2(acc[2][1], aB.x, rr.y);
            ffma2(acc[3][0], aB.y, rr.x); ffma2(acc[3][1], aB.y, rr.y);
        }
    }

    // reduce partial M into global accumulator
#pragma unroll
    for (int u = 0; u < 4; u++) {
#pragma unroll
        for (int jp = 0; jp < 2; jp++) {
            float lo, hi;
            unpack2(acc[u][jp], lo, hi);
            const int row = tu4 + u, col = tj4 + 2 * jp;
            atomicAdd(&g_Maccum[row * 64 + col],     lo);
            atomicAdd(&g_Maccum[row * 64 + col + 1], hi);
        }
    }
}

// ---------------------------------------------------------------------------
// Stage 2 (tiny): product = W2^T M ; t = sigmoid(product + b_s) ;
// S = V_s @ t ; out = softmax over rows (axis 1) per column.
// Single CTA, blockDim (64, 4).
// ---------------------------------------------------------------------------
__global__ void stage2_kernel(const float *__restrict__ W2,
                              const float *__restrict__ b_s,
                              const float *__restrict__ V_s,
                              float *__restrict__ out) {
    __shared__ float Ms[64 * 64];    // reused as S after t is computed
    __shared__ float tsh[60 * 64];
    __shared__ float W2s[3600];

    const int tx = threadIdx.x, ty = threadIdx.y;
    const int tid = ty * 64 + tx;

    for (int i = tid; i < 64 * 64; i += 256) Ms[i] = g_Maccum[i];
    for (int i = tid; i < 3600;    i += 256) W2s[i] = W2[i];
    __syncthreads();

    if (tx < 60) {
        for (int i = ty; i < 60; i += 4) {
            float p = 0.0f;
            for (int u = 0; u < 60; u++)
                p = fmaf(W2s[u * 60 + i], Ms[u * 64 + tx], p);
            p += b_s[i * 60 + tx];
            tsh[i * 64 + tx] = 1.0f / (1.0f + __expf(-p));
        }
    }
    __syncthreads();

    float *Ssh = Ms;   // Ms no longer needed
    if (tx < 60) {
        for (int i = ty; i < 60; i += 4) {
            float s = 0.0f;
            for (int k = 0; k < 60; k++)
                s = fmaf(V_s[i * 60 + k], tsh[k * 64 + tx], s);
            Ssh[i * 64 + tx] = s;
        }
    }
    __syncthreads();

    if (ty == 0 && tx < 60) {
        float m = -1e30f;
        for (int i = 0; i < 60; i++) m = fmaxf(m, Ssh[i * 64 + tx]);
        float sum = 0.0f;
        for (int i = 0; i < 60; i++) sum += __expf(Ssh[i * 64 + tx] - m);
        const float inv = 1.0f / sum;
        for (int i = 0; i < 60; i++)
            out[i * 60 + tx] = __expf(Ssh[i * 64 + tx] - m) * inv;
    }
}

// ---------------------------------------------------------------------------
extern "C" void kernel_launch(void *const *d_in, const int *in_sizes, int n_in,
                              void *d_out, int out_size) {
    const float *x  = (const float *)d_in[0];
    const float *W1 = (const float *)d_in[1];
    const float *W2 = (const float *)d_in[2];
    const float *W3 = (const float *)d_in[3];
    const float *bs = (const float *)d_in[4];
    const float *Vs = (const float *)d_in[5];
    float *out = (float *)d_out;

    const int B = in_sizes[0] / 300;     // 131072
    const int nCTA = B / BPC;            // 512

    zero_kernel<<<16, 256>>>();
    stage1_kernel<<<nCTA, NTHREADS>>>(x, W1, W3);
    stage2_kernel<<<1, dim3(64, 4)>>>(W2, bs, Vs, out);
}

// round 8
// speedup vs baseline: 1.0235x; 1.0235x over previous
#include <cuda_runtime.h>

// ---------------------------------------------------------------------------
// Spatial_Attention_layer, fully fused single kernel.
// out = softmax_axis1( V_s @ sigmoid(W2^T M + b_s) )
//   M[u][j] = sum_b a_b[u]*r_b[j],  a_b[v] = sum_t W1[t] x[b,t,v],
//   r_b[v] = sum_t W3[t] x[b,t,v].  B=131072, T=5, V=60 (padded 64).
// Stage 1: 512 CTAs stream x (157 MB) with a 4-deep cp.async pipeline and
//          accumulate rank-1 updates into per-thread 4x4 FFMA2 tiles.
// Tail:    atomicAdd into __device__ M; last CTA runs the O(60^3) epilogue,
//          writes out, and re-zeros state for the next graph replay.
// ---------------------------------------------------------------------------

#define NTHREADS 256
#define GRP       8               // batches per pipeline stage
#define BPC      256              // batches per CTA
#define NGRP     (BPC / GRP)      // 32
#define F4PG     (GRP * 75)       // 600 float4 per stage
#define DEPTH     4               // pipeline depth

typedef unsigned long long u64;

__device__ float        g_Maccum[64 * 64];   // zero at module load; re-zeroed per run
__device__ unsigned int g_ctr;               // CTA completion counter

// ---- packed f32x2 helpers (FFMA2 only reachable via PTX) -------------------
__device__ __forceinline__ void ffma2(u64 &d, u64 a, u64 b) {
    asm("fma.rn.f32x2 %0, %1, %2, %3;" : "=l"(d) : "l"(a), "l"(b), "l"(d));
}
__device__ __forceinline__ void unpack2(u64 v, float &lo, float &hi) {
    asm("mov.b64 {%0, %1}, %2;" : "=f"(lo), "=f"(hi) : "l"(v));
}

// ---- cp.async helpers ------------------------------------------------------
__device__ __forceinline__ void cp_async16(void *smem, const void *g) {
    unsigned saddr = (unsigned)__cvta_generic_to_shared(smem);
    asm volatile("cp.async.cg.shared.global [%0], [%1], 16;" :: "r"(saddr), "l"(g));
}
__device__ __forceinline__ void cp_commit() { asm volatile("cp.async.commit_group;"); }
template <int N>
__device__ __forceinline__ void cp_wait() { asm volatile("cp.async.wait_group %0;" :: "n"(N)); }

struct S1 {
    float4 xs[DEPTH][F4PG];   // 4 x 9.6 KB = 38.4 KB
    float2 a2s[GRP][64];      // a pre-duplicated {a,a}  4 KB
    float  rs[GRP][64];       // 2 KB
};
struct S2 {
    float Ms[64 * 64];        // 16 KB (reused as S)
    float tsh[60 * 64];       // 15 KB
    float W2s[3600];          // 14 KB
};
union SMem { S1 s1; S2 s2; };

__device__ __forceinline__ void stage_group(float4 *dst, const float4 *src, int tid) {
    // 600 float4 over 256 threads: 2 full passes + partial third (tid < 88)
    cp_async16(dst + tid,       src + tid);
    cp_async16(dst + tid + 256, src + tid + 256);
    if (tid < F4PG - 512) cp_async16(dst + tid + 512, src + tid + 512);
}

// ---------------------------------------------------------------------------
__global__ void __launch_bounds__(NTHREADS, 4)
fused_kernel(const float *__restrict__ x,
             const float *__restrict__ W1p,
             const float *__restrict__ W3p,
             const float *__restrict__ W2,
             const float *__restrict__ b_s,
             const float *__restrict__ V_s,
             float *__restrict__ out,
             int nCTA) {
    __shared__ SMem sm;

    const int tid = threadIdx.x;
    const long base_batch = (long)blockIdx.x * BPC;
    const float4 *gx = (const float4 *)x + base_batch * 75;   // 75 f4 / batch

    float w1[5], w3[5];
#pragma unroll
    for (int t = 0; t < 5; t++) { w1[t] = W1p[t]; w3[t] = W3p[t]; }

    u64 acc[4][2];
#pragma unroll
    for (int u = 0; u < 4; u++) { acc[u][0] = 0ull; acc[u][1] = 0ull; }

    const int tu4 = (tid >> 4) * 4;   // row block  (0..60 step 4)
    const int tj4 = (tid & 15) * 4;   // col block  (0..60 step 4)

    // prologue: stage groups 0..DEPTH-2
#pragma unroll
    for (int d = 0; d < DEPTH - 1; d++) {
        stage_group(sm.s1.xs[d], gx + (long)d * F4PG, tid);
        cp_commit();
    }

    for (int grp = 0; grp < NGRP; grp++) {
        const int buf = grp & (DEPTH - 1);
        if (grp + DEPTH - 1 < NGRP)
            stage_group(sm.s1.xs[(grp + DEPTH - 1) & (DEPTH - 1)],
                        gx + (long)(grp + DEPTH - 1) * F4PG, tid);
        cp_commit();                 // possibly-empty group keeps the count uniform
        cp_wait<DEPTH - 1>();        // group `grp` complete
        __syncthreads();             // xs[buf] visible; prev iter done with a2s/rs

        // a (duplicated) and r for the GRP staged batches: exactly 2 passes
#pragma unroll
        for (int it = 0; it < (GRP * 64) / NTHREADS; it++) {
            const int idx = tid + it * NTHREADS;
            const int g = idx >> 6, v = idx & 63;
            float s1 = 0.0f, s3 = 0.0f;
            if (v < 60) {
                const float *xb = ((const float *)&sm.s1.xs[buf][0]) + g * 300;
#pragma unroll
                for (int t = 0; t < 5; t++) {
                    const float xv = xb[t * 60 + v];
                    s1 = fmaf(w1[t], xv, s1);
                    s3 = fmaf(w3[t], xv, s3);
                }
            }
            sm.s1.a2s[g][v] = make_float2(s1, s1);
            sm.s1.rs[g][v]  = s3;
        }
        __syncthreads();

        // rank-1 updates: 3 x LDS.128 + 8 x FFMA2 per batch per thread
#pragma unroll 2
        for (int g = 0; g < GRP; g++) {
            const ulonglong2 *pa = (const ulonglong2 *)&sm.s1.a2s[g][tu4];
            const ulonglong2 aA = pa[0];
            const ulonglong2 aB = pa[1];
            const ulonglong2 rr = *(const ulonglong2 *)&sm.s1.rs[g][tj4];
            ffma2(acc[0][0], aA.x, rr.x); ffma2(acc[0][1], aA.x, rr.y);
            ffma2(acc[1][0], aA.y, rr.x); ffma2(acc[1][1], aA.y, rr.y);
            ffma2(acc[2][0], aB.x, rr.x); ffma2(acc[2][1], aB.x, rr.y);
            ffma2(acc[3][0], aB.y, rr.x); ffma2(acc[3][1], aB.y, rr.y);
        }
    }

    // reduce partial M into global accumulator
#pragma unroll
    for (int u = 0; u < 4; u++) {
#pragma unroll
        for (int jp = 0; jp < 2; jp++) {
            float lo, hi;
            unpack2(acc[u][jp], lo, hi);
            const int row = tu4 + u, col = tj4 + 2 * jp;
            atomicAdd(&g_Maccum[row * 64 + col],     lo);
            atomicAdd(&g_Maccum[row * 64 + col + 1], hi);
        }
    }

    // ---- completion protocol: last CTA runs the epilogue -------------------
    __threadfence();
    __shared__ unsigned int s_rank;
    __syncthreads();                 // all atomics of this CTA issued
    if (tid == 0) s_rank = atomicAdd(&g_ctr, 1u);
    __syncthreads();
    if (s_rank != (unsigned)(nCTA - 1)) return;

    // =========================== epilogue (1 CTA) ==========================
    __threadfence();                 // acquire side
    float *Ms  = sm.s2.Ms;
    float *tsh = sm.s2.tsh;
    float *W2s = sm.s2.W2s;

    for (int i = tid; i < 64 * 64; i += NTHREADS) Ms[i] = __ldcg(&g_Maccum[i]);
    for (int i = tid; i < 3600;    i += NTHREADS) W2s[i] = W2[i];
    __syncthreads();

    // reset global state for the next graph replay (after Ms is in smem)
    for (int i = tid; i < 64 * 64; i += NTHREADS) g_Maccum[i] = 0.0f;
    if (tid == 0) g_ctr = 0u;

    const int tx = tid & 63;         // column
    const int ty = tid >> 6;         // 0..3

    // product = W2^T M ; t = sigmoid(product + b_s)
    if (tx < 60) {
        for (int i = ty; i < 60; i += 4) {
            float p = 0.0f;
            for (int u = 0; u < 60; u++)
                p = fmaf(W2s[u * 60 + i], Ms[u * 64 + tx], p);
            p += b_s[i * 60 + tx];
            tsh[i * 64 + tx] = 1.0f / (1.0f + __expf(-p));
        }
    }
    __syncthreads();

    // S = V_s @ t  (written over Ms)
    if (tx < 60) {
        for (int i = ty; i < 60; i += 4) {
            float s = 0.0f;
            for (int k = 0; k < 60; k++)
                s = fmaf(V_s[i * 60 + k], tsh[k * 64 + tx], s);
            Ms[i * 64 + tx] = s;
        }
    }
    __syncthreads();

    // column softmax over rows (axis 1)
    if (ty == 0 && tx < 60) {
        float m = -1e30f;
        for (int i = 0; i < 60; i++) m = fmaxf(m, Ms[i * 64 + tx]);
        float sum = 0.0f;
        for (int i = 0; i < 60; i++) {
            const float e = __expf(Ms[i * 64 + tx] - m);
            tsh[i * 64 + tx] = e;
            sum += e;
        }
        const float inv = 1.0f / sum;
        for (int i = 0; i < 60; i++)
            out[i * 60 + tx] = tsh[i * 64 + tx] * inv;
    }
}

// ---------------------------------------------------------------------------
extern "C" void kernel_launch(void *const *d_in, const int *in_sizes, int n_in,
                              void *d_out, int out_size) {
    const float *x  = (const float *)d_in[0];
    const float *W1 = (const float *)d_in[1];
    const float *W2 = (const float *)d_in[2];
    const float *W3 = (const float *)d_in[3];
    const float *bs = (const float *)d_in[4];
    const float *Vs = (const float *)d_in[5];
    float *out = (float *)d_out;

    const int B = in_sizes[0] / 300;     // 131072
    const int nCTA = B / BPC;            // 512

    fused_kernel<<<nCTA, NTHREADS>>>(x, W1, W3, W2, bs, Vs, out, nCTA);
}